// round 6
// baseline (speedup 1.0000x reference)
#include <cuda_runtime.h>
#include <math.h>

#define MAXN 100000
#define MAXE 1800000   // E + N with slack

// ---------------- scratch (device globals) ----------------
__device__ int   g_cnt[MAXN];
__device__ int   g_off[MAXN + 1];
__device__ int   g_cur[MAXN];
__device__ int   g_csr[MAXE];
__device__ float g_h1[MAXN * 64];
__device__ float g_as1[MAXN * 8];
__device__ float g_ad1[MAXN * 8];
__device__ float g_x2[MAXN * 64];
__device__ float g_h2[MAXN * 64];
__device__ float g_as2[MAXN];
__device__ float g_ad2[MAXN];

// ---------------- CSR build ----------------
__global__ void count_k(const int* __restrict__ ei, int E) {
    int e = blockIdx.x * blockDim.x + threadIdx.x;
    if (e < E) atomicAdd(&g_cnt[ei[E + e]], 1);   // dst row of edge_index
}

// single block, 1024 threads: exclusive scan of (cnt[i]+1) [+1 = self loop],
// writes offsets, pre-places the self-loop, initializes fill cursors.
__global__ void scan_k(int n, int etot) {
    __shared__ int sums[1024];
    int t = threadIdx.x;
    int chunk = (n + 1023) >> 10;
    int b = t * chunk;
    int e = min(n, b + chunk);
    int s = 0;
    for (int i = b; i < e; i++) s += g_cnt[i] + 1;
    sums[t] = s;
    __syncthreads();
    for (int o = 1; o < 1024; o <<= 1) {
        int xv = (t >= o) ? sums[t - o] : 0;
        __syncthreads();
        sums[t] += xv;
        __syncthreads();
    }
    int run = (t == 0) ? 0 : sums[t - 1];
    for (int i = b; i < e; i++) {
        g_off[i] = run;
        g_csr[run] = i;        // self loop occupies first slot
        g_cur[i] = run + 1;
        run += g_cnt[i] + 1;
    }
    if (t == 0) g_off[n] = etot;
}

__global__ void fill_k(const int* __restrict__ ei, int E) {
    int e = blockIdx.x * blockDim.x + threadIdx.x;
    if (e < E) {
        int s = ei[e];
        int d = ei[E + e];
        int pos = atomicAdd(&g_cur[d], 1);
        g_csr[pos] = s;
    }
}

// ---------------- GEMM 1: h1 = x @ W1  (K=128, 64 cols), fused alpha1 ----------------
__global__ void gemm1_k(const float* __restrict__ x, const float* __restrict__ W,
                        const float* __restrict__ a_src, const float* __restrict__ a_dst,
                        int n) {
    __shared__ float Ws[128 * 64];   // 32 KB
    __shared__ float Xs[32 * 128];   // 16 KB
    int tid = threadIdx.x;           // 256 threads
    int r0 = blockIdx.x * 32;

    const float4* W4 = (const float4*)W;
    float4* Ws4 = (float4*)Ws;
    for (int i = tid; i < 128 * 64 / 4; i += 256) Ws4[i] = W4[i];

    int rows = min(32, n - r0);
    const float4* X4 = (const float4*)(x + (size_t)r0 * 128);
    float4* Xs4 = (float4*)Xs;
    for (int i = tid; i < rows * 32; i += 256) Xs4[i] = X4[i];
    __syncthreads();

    int col = tid & 63;
    int rg = tid >> 6;               // 4 row-groups of 8 rows
    float acc[8] = {0, 0, 0, 0, 0, 0, 0, 0};
    for (int k = 0; k < 128; k += 4) {
        float w0 = Ws[(k + 0) * 64 + col];
        float w1 = Ws[(k + 1) * 64 + col];
        float w2 = Ws[(k + 2) * 64 + col];
        float w3 = Ws[(k + 3) * 64 + col];
#pragma unroll
        for (int r = 0; r < 8; r++) {
            float4 xv = *(const float4*)&Xs[(rg * 8 + r) * 128 + k];
            acc[r] += xv.x * w0 + xv.y * w1 + xv.z * w2 + xv.w * w3;
        }
    }
    float asv = a_src[col];          // (H1,C1)=(8,8) flattened: index h*8+c == col
    float adv = a_dst[col];
    int h = col >> 3;
#pragma unroll
    for (int r = 0; r < 8; r++) {
        int row = r0 + rg * 8 + r;
        bool ok = row < n;
        if (ok) g_h1[(size_t)row * 64 + col] = acc[r];
        float s = acc[r] * asv;
        float d = acc[r] * adv;
#pragma unroll
        for (int o = 1; o < 8; o <<= 1) {
            s += __shfl_xor_sync(0xffffffffu, s, o);
            d += __shfl_xor_sync(0xffffffffu, d, o);
        }
        if (ok && (col & 7) == 0) {
            g_as1[(size_t)row * 8 + h] = s;
            g_ad1[(size_t)row * 8 + h] = d;
        }
    }
}

// ---------------- GEMM 2: h2 = x2 @ W2  (K=64, 64 cols), fused alpha2 ----------------
__global__ void gemm2_k(const float* __restrict__ W,
                        const float* __restrict__ a_src, const float* __restrict__ a_dst,
                        int n) {
    __shared__ float Ws[64 * 64];    // 16 KB
    __shared__ float Xs[32 * 64];    // 8 KB
    __shared__ float redS[8][8];     // [warp][r]
    __shared__ float redD[8][8];
    int tid = threadIdx.x;
    int r0 = blockIdx.x * 32;

    const float4* W4 = (const float4*)W;
    float4* Ws4 = (float4*)Ws;
    for (int i = tid; i < 64 * 64 / 4; i += 256) Ws4[i] = W4[i];

    int rows = min(32, n - r0);
    const float4* X4 = (const float4*)(&g_x2[(size_t)r0 * 64]);
    float4* Xs4 = (float4*)Xs;
    for (int i = tid; i < rows * 16; i += 256) Xs4[i] = X4[i];
    __syncthreads();

    int col = tid & 63;
    int rg = tid >> 6;
    float acc[8] = {0, 0, 0, 0, 0, 0, 0, 0};
    for (int k = 0; k < 64; k += 4) {
        float w0 = Ws[(k + 0) * 64 + col];
        float w1 = Ws[(k + 1) * 64 + col];
        float w2 = Ws[(k + 2) * 64 + col];
        float w3 = Ws[(k + 3) * 64 + col];
#pragma unroll
        for (int r = 0; r < 8; r++) {
            float4 xv = *(const float4*)&Xs[(rg * 8 + r) * 64 + k];
            acc[r] += xv.x * w0 + xv.y * w1 + xv.z * w2 + xv.w * w3;
        }
    }
    float asv = a_src[col];
    float adv = a_dst[col];
    int w = tid >> 5, lane = tid & 31;
#pragma unroll
    for (int r = 0; r < 8; r++) {
        int row = r0 + rg * 8 + r;
        if (row < n) g_h2[(size_t)row * 64 + col] = acc[r];
        float s = acc[r] * asv;
        float d = acc[r] * adv;
#pragma unroll
        for (int o = 16; o; o >>= 1) {
            s += __shfl_xor_sync(0xffffffffu, s, o);
            d += __shfl_xor_sync(0xffffffffu, d, o);
        }
        if (lane == 0) { redS[w][r] = s; redD[w][r] = d; }
    }
    __syncthreads();
    if (tid < 32) {                  // row = r0 + tid  (rg=tid>>3, r=tid&7)
        int row = r0 + tid;
        if (row < n) {
            int wa = (tid >> 3) * 2, r = tid & 7;
            g_as2[row] = redS[wa][r] + redS[wa + 1][r];
            g_ad2[row] = redD[wa][r] + redD[wa + 1][r];
        }
    }
}

// ---------------- layer-1 aggregation (+bias, +ELU) ----------------
// 64 threads per node; softmax folded; x4 unroll with independent accumulators
// so 4 csr loads + 8 gathers are in flight per thread.
__global__ void agg1_k(const float* __restrict__ b1, int n) {
    int t = threadIdx.x & 63;
    int node = blockIdx.x * 4 + (threadIdx.x >> 6);
    if (node >= n) return;
    int h = t >> 3;
    int beg = g_off[node], end = g_off[node + 1];
    float adv = g_ad1[(size_t)node * 8 + h];
    float acc0 = 0.f, acc1 = 0.f, acc2 = 0.f, acc3 = 0.f;
    float den0 = 0.f, den1 = 0.f, den2 = 0.f, den3 = 0.f;
    int j = beg;
    for (; j + 3 < end; j += 4) {
        int s0 = g_csr[j];
        int s1 = g_csr[j + 1];
        int s2 = g_csr[j + 2];
        int s3 = g_csr[j + 3];
        float e0 = g_as1[(size_t)s0 * 8 + h] + adv;
        float e1 = g_as1[(size_t)s1 * 8 + h] + adv;
        float e2 = g_as1[(size_t)s2 * 8 + h] + adv;
        float e3 = g_as1[(size_t)s3 * 8 + h] + adv;
        float v0 = g_h1[(size_t)s0 * 64 + t];
        float v1 = g_h1[(size_t)s1 * 64 + t];
        float v2 = g_h1[(size_t)s2 * 64 + t];
        float v3 = g_h1[(size_t)s3 * 64 + t];
        e0 = (e0 > 0.f) ? e0 : 0.2f * e0;
        e1 = (e1 > 0.f) ? e1 : 0.2f * e1;
        e2 = (e2 > 0.f) ? e2 : 0.2f * e2;
        e3 = (e3 > 0.f) ? e3 : 0.2f * e3;
        float p0 = __expf(e0);
        float p1 = __expf(e1);
        float p2 = __expf(e2);
        float p3 = __expf(e3);
        den0 += p0; den1 += p1; den2 += p2; den3 += p3;
        acc0 += p0 * v0;
        acc1 += p1 * v1;
        acc2 += p2 * v2;
        acc3 += p3 * v3;
    }
    for (; j < end; j++) {
        int s0 = g_csr[j];
        float e0 = g_as1[(size_t)s0 * 8 + h] + adv;
        e0 = (e0 > 0.f) ? e0 : 0.2f * e0;
        float p0 = __expf(e0);
        den0 += p0;
        acc0 += p0 * g_h1[(size_t)s0 * 64 + t];
    }
    float den = (den0 + den1) + (den2 + den3);
    float acc = (acc0 + acc1) + (acc2 + acc3);
    float v = __fdividef(acc, den + 1e-16f) + b1[t];
    v = (v > 0.f) ? v : expm1f(v);   // ELU
    g_x2[(size_t)node * 64 + t] = v;
}

// ---------------- layer-2 aggregation + log_softmax ----------------
__global__ void agg2_k(const float* __restrict__ b2, float* __restrict__ out, int n) {
    __shared__ float red[8];
    int t = threadIdx.x & 63;
    int local = threadIdx.x >> 6;    // node slot within block (0..3)
    int node = blockIdx.x * 4 + local;
    bool act = node < n;
    float v = 0.f;
    if (act) {
        int beg = g_off[node], end = g_off[node + 1];
        float adv = g_ad2[node];
        float acc0 = 0.f, acc1 = 0.f, acc2 = 0.f, acc3 = 0.f;
        float den0 = 0.f, den1 = 0.f, den2 = 0.f, den3 = 0.f;
        int j = beg;
        for (; j + 3 < end; j += 4) {
            int s0 = g_csr[j];
            int s1 = g_csr[j + 1];
            int s2 = g_csr[j + 2];
            int s3 = g_csr[j + 3];
            float e0 = g_as2[s0] + adv;
            float e1 = g_as2[s1] + adv;
            float e2 = g_as2[s2] + adv;
            float e3 = g_as2[s3] + adv;
            float v0 = g_h2[(size_t)s0 * 64 + t];
            float v1 = g_h2[(size_t)s1 * 64 + t];
            float v2 = g_h2[(size_t)s2 * 64 + t];
            float v3 = g_h2[(size_t)s3 * 64 + t];
            e0 = (e0 > 0.f) ? e0 : 0.2f * e0;
            e1 = (e1 > 0.f) ? e1 : 0.2f * e1;
            e2 = (e2 > 0.f) ? e2 : 0.2f * e2;
            e3 = (e3 > 0.f) ? e3 : 0.2f * e3;
            float p0 = __expf(e0);
            float p1 = __expf(e1);
            float p2 = __expf(e2);
            float p3 = __expf(e3);
            den0 += p0; den1 += p1; den2 += p2; den3 += p3;
            acc0 += p0 * v0;
            acc1 += p1 * v1;
            acc2 += p2 * v2;
            acc3 += p3 * v3;
        }
        for (; j < end; j++) {
            int s0 = g_csr[j];
            float e0 = g_as2[s0] + adv;
            e0 = (e0 > 0.f) ? e0 : 0.2f * e0;
            float p0 = __expf(e0);
            den0 += p0;
            acc0 += p0 * g_h2[(size_t)s0 * 64 + t];
        }
        float den = (den0 + den1) + (den2 + den3);
        float acc = (acc0 + acc1) + (acc2 + acc3);
        v = __fdividef(acc, den + 1e-16f) + b2[t];
    }
    // log_softmax across the 64 threads (2 warps) of this node
    int wh = (threadIdx.x >> 5) & 1;
    float m = v;
#pragma unroll
    for (int o = 16; o; o >>= 1) m = fmaxf(m, __shfl_xor_sync(0xffffffffu, m, o));
    if ((threadIdx.x & 31) == 0) red[local * 2 + wh] = m;
    __syncthreads();
    m = fmaxf(red[local * 2], red[local * 2 + 1]);
    __syncthreads();
    float p = __expf(v - m);
#pragma unroll
    for (int o = 16; o; o >>= 1) p += __shfl_xor_sync(0xffffffffu, p, o);
    if ((threadIdx.x & 31) == 0) red[local * 2 + wh] = p;
    __syncthreads();
    float tot = red[local * 2] + red[local * 2 + 1];
    if (act) out[(size_t)node * 64 + t] = v - m - logf(tot);
}

// ---------------- launch ----------------
extern "C" void kernel_launch(void* const* d_in, const int* in_sizes, int n_in,
                              void* d_out, int out_size) {
    const float* x   = (const float*)d_in[0];
    const int*   ei  = (const int*)  d_in[1];
    const float* W1  = (const float*)d_in[2];
    const float* as1 = (const float*)d_in[3];
    const float* ad1 = (const float*)d_in[4];
    const float* b1  = (const float*)d_in[5];
    const float* W2  = (const float*)d_in[6];
    const float* as2 = (const float*)d_in[7];
    const float* ad2 = (const float*)d_in[8];
    const float* b2  = (const float*)d_in[9];

    int n = in_sizes[0] / 128;
    int E = in_sizes[1] / 2;

    // CSR by destination (shared by both layers)
    void* cnt_ptr = nullptr;
    cudaGetSymbolAddress(&cnt_ptr, g_cnt);
    cudaMemsetAsync(cnt_ptr, 0, (size_t)n * sizeof(int));
    count_k<<<(E + 255) / 256, 256>>>(ei, E);
    scan_k<<<1, 1024>>>(n, E + n);
    fill_k<<<(E + 255) / 256, 256>>>(ei, E);

    // Layer 1 (alpha1 fused into gemm1 epilogue)
    gemm1_k<<<(n + 31) / 32, 256>>>(x, W1, as1, ad1, n);
    agg1_k<<<(n + 3) / 4, 256>>>(b1, n);

    // Layer 2 (alpha2 fused into gemm2 epilogue)
    gemm2_k<<<(n + 31) / 32, 256>>>(W2, as2, ad2, n);
    agg2_k<<<(n + 3) / 4, 256>>>(b2, (float*)d_out, n);
}

// round 8
// speedup vs baseline: 2.3633x; 2.3633x over previous
#include <cuda_runtime.h>
#include <math.h>

#define MAXN 100000
#define MAXE 1800000   // E + N with slack

// ---------------- scratch (device globals) ----------------
__device__ int   g_cnt[MAXN];
__device__ int   g_off[MAXN + 1];
__device__ int   g_cur[MAXN];
__device__ int   g_csr[MAXE];
__device__ int   g_bsum[512];
__device__ int   g_boff[512];
__device__ float g_h1[MAXN * 64];
__device__ float g_as1[MAXN * 8];
__device__ float g_ad1[MAXN * 8];
__device__ float g_x2[MAXN * 64];
__device__ float g_h2[MAXN * 64];
__device__ float g_as2[MAXN];
__device__ float g_ad2[MAXN];

// ---------------- CSR build ----------------
__global__ void count_k(const int* __restrict__ ei, int E) {
    int e = blockIdx.x * blockDim.x + threadIdx.x;
    if (e < E) atomicAdd(&g_cnt[ei[E + e]], 1);   // dst row of edge_index
}

// block sums of (cnt+1)
__global__ void bsum_k(int n) {
    __shared__ int ws[8];
    int i = blockIdx.x * 256 + threadIdx.x;
    int v = (i < n) ? g_cnt[i] + 1 : 0;
#pragma unroll
    for (int o = 16; o; o >>= 1) v += __shfl_xor_sync(0xffffffffu, v, o);
    if ((threadIdx.x & 31) == 0) ws[threadIdx.x >> 5] = v;
    __syncthreads();
    if (threadIdx.x == 0) {
        int s = 0;
#pragma unroll
        for (int w = 0; w < 8; w++) s += ws[w];
        g_bsum[blockIdx.x] = s;
    }
}

// exclusive scan of block sums (nb <= 512), single tiny block
__global__ void bscan_k(int nb) {
    __shared__ int s[512];
    int t = threadIdx.x;
    int v = (t < nb) ? g_bsum[t] : 0;
    s[t] = v;
    __syncthreads();
    for (int o = 1; o < 512; o <<= 1) {
        int xv = (t >= o) ? s[t - o] : 0;
        __syncthreads();
        s[t] += xv;
        __syncthreads();
    }
    if (t < nb) g_boff[t] = s[t] - v;   // exclusive
}

// block-internal exclusive scan + emit offsets, self-loop, cursors
__global__ void emit_k(int n, int etot) {
    __shared__ int wsum[8];
    int i = blockIdx.x * 256 + threadIdx.x;
    int lane = threadIdx.x & 31, w = threadIdx.x >> 5;
    int v = (i < n) ? g_cnt[i] + 1 : 0;
    int inc = v;
#pragma unroll
    for (int o = 1; o < 32; o <<= 1) {
        int xv = __shfl_up_sync(0xffffffffu, inc, o);
        if (lane >= o) inc += xv;
    }
    if (lane == 31) wsum[w] = inc;
    __syncthreads();
    if (threadIdx.x == 0) {
        int run = 0;
#pragma unroll
        for (int k = 0; k < 8; k++) { int tmp = wsum[k]; wsum[k] = run; run += tmp; }
    }
    __syncthreads();
    int excl = g_boff[blockIdx.x] + wsum[w] + (inc - v);
    if (i < n) {
        g_off[i] = excl;
        g_csr[excl] = i;       // self loop first
        g_cur[i] = excl + 1;
    }
    if (blockIdx.x == 0 && threadIdx.x == 0) g_off[n] = etot;
}

__global__ void fill_k(const int* __restrict__ ei, int E) {
    int e = blockIdx.x * blockDim.x + threadIdx.x;
    if (e < E) {
        int s = ei[e];
        int d = ei[E + e];
        int pos = atomicAdd(&g_cur[d], 1);
        g_csr[pos] = s;
    }
}

// ---------------- GEMM 1: h1 = x @ W1 (K=128), fused alpha1 ----------------
// 128 threads, 64 rows x 64 cols per block; each thread: 4 cols x 8 rows.
// K processed in two halves so Xs fits 16KB (total static smem 48KB).
__global__ void __launch_bounds__(128) gemm1_k(
        const float* __restrict__ x, const float* __restrict__ W,
        const float* __restrict__ a_src, const float* __restrict__ a_dst, int n) {
    __shared__ float Ws[128 * 64];   // 32 KB (full W)
    __shared__ float Xs[64 * 64];    // 16 KB (one K-half of 64 rows)
    int tid = threadIdx.x;
    int r0 = blockIdx.x * 64;

    const float4* W4 = (const float4*)W;
    float4* Ws4 = (float4*)Ws;
    for (int i = tid; i < 128 * 64 / 4; i += 128) Ws4[i] = W4[i];

    int rows = min(64, n - r0);
    int col4 = (tid & 15) * 4;
    int rg = tid >> 4;               // 8 row-groups of 8 rows
    float acc[8][4];
#pragma unroll
    for (int r = 0; r < 8; r++) { acc[r][0] = acc[r][1] = acc[r][2] = acc[r][3] = 0.f; }

    for (int half = 0; half < 2; half++) {
        __syncthreads();             // covers Ws readiness (iter 0) and Xs reuse
        for (int i = tid; i < rows * 16; i += 128) {
            int rr = i >> 4, seg = i & 15;
            ((float4*)Xs)[i] = *(const float4*)&x[(size_t)(r0 + rr) * 128 + half * 64 + seg * 4];
        }
        __syncthreads();
        int kb = half * 64;
        for (int k = 0; k < 64; k += 4) {
            float4 w0 = *(float4*)&Ws[(kb + k + 0) * 64 + col4];
            float4 w1 = *(float4*)&Ws[(kb + k + 1) * 64 + col4];
            float4 w2 = *(float4*)&Ws[(kb + k + 2) * 64 + col4];
            float4 w3 = *(float4*)&Ws[(kb + k + 3) * 64 + col4];
#pragma unroll
            for (int r = 0; r < 8; r++) {
                float4 xv = *(float4*)&Xs[(rg * 8 + r) * 64 + k];
                acc[r][0] += xv.x * w0.x + xv.y * w1.x + xv.z * w2.x + xv.w * w3.x;
                acc[r][1] += xv.x * w0.y + xv.y * w1.y + xv.z * w2.y + xv.w * w3.y;
                acc[r][2] += xv.x * w0.z + xv.y * w1.z + xv.z * w2.z + xv.w * w3.z;
                acc[r][3] += xv.x * w0.w + xv.y * w1.w + xv.z * w2.w + xv.w * w3.w;
            }
        }
    }

    // epilogue: store h1 + alpha1 (head h = cols 8h..8h+7 = lane pair (2h,2h+1) of each 16-group)
    float4 a_s = *(const float4*)&a_src[col4];
    float4 a_d = *(const float4*)&a_dst[col4];
    int lane = tid & 31;
#pragma unroll
    for (int r = 0; r < 8; r++) {
        int row = r0 + rg * 8 + r;
        bool ok = row < n;
        if (ok) *(float4*)&g_h1[(size_t)row * 64 + col4] =
            make_float4(acc[r][0], acc[r][1], acc[r][2], acc[r][3]);
        float s = acc[r][0] * a_s.x + acc[r][1] * a_s.y + acc[r][2] * a_s.z + acc[r][3] * a_s.w;
        float d = acc[r][0] * a_d.x + acc[r][1] * a_d.y + acc[r][2] * a_d.z + acc[r][3] * a_d.w;
        s += __shfl_xor_sync(0xffffffffu, s, 1);
        d += __shfl_xor_sync(0xffffffffu, d, 1);
        if (ok && !(lane & 1)) {
            int h = (lane & 15) >> 1;
            g_as1[(size_t)row * 8 + h] = s;
            g_ad1[(size_t)row * 8 + h] = d;
        }
    }
}

// ---------------- GEMM 2: h2 = x2 @ W2 (K=64), fused alpha2 ----------------
__global__ void __launch_bounds__(128) gemm2_k(
        const float* __restrict__ W,
        const float* __restrict__ a_src, const float* __restrict__ a_dst, int n) {
    __shared__ float Ws[64 * 64];    // 16 KB
    __shared__ float Xs[64 * 64];    // 16 KB
    int tid = threadIdx.x;
    int r0 = blockIdx.x * 64;

    const float4* W4 = (const float4*)W;
    float4* Ws4 = (float4*)Ws;
    for (int i = tid; i < 64 * 64 / 4; i += 128) Ws4[i] = W4[i];

    int rows = min(64, n - r0);
    for (int i = tid; i < rows * 16; i += 128)
        ((float4*)Xs)[i] = *(const float4*)&g_x2[(size_t)r0 * 64 + i * 4];
    __syncthreads();

    int col4 = (tid & 15) * 4;
    int rg = tid >> 4;
    float acc[8][4];
#pragma unroll
    for (int r = 0; r < 8; r++) { acc[r][0] = acc[r][1] = acc[r][2] = acc[r][3] = 0.f; }

    for (int k = 0; k < 64; k += 4) {
        float4 w0 = *(float4*)&Ws[(k + 0) * 64 + col4];
        float4 w1 = *(float4*)&Ws[(k + 1) * 64 + col4];
        float4 w2 = *(float4*)&Ws[(k + 2) * 64 + col4];
        float4 w3 = *(float4*)&Ws[(k + 3) * 64 + col4];
#pragma unroll
        for (int r = 0; r < 8; r++) {
            float4 xv = *(float4*)&Xs[(rg * 8 + r) * 64 + k];
            acc[r][0] += xv.x * w0.x + xv.y * w1.x + xv.z * w2.x + xv.w * w3.x;
            acc[r][1] += xv.x * w0.y + xv.y * w1.y + xv.z * w2.y + xv.w * w3.y;
            acc[r][2] += xv.x * w0.z + xv.y * w1.z + xv.z * w2.z + xv.w * w3.z;
            acc[r][3] += xv.x * w0.w + xv.y * w1.w + xv.z * w2.w + xv.w * w3.w;
        }
    }

    // epilogue: store h2 + alpha2 (64-wide dot per row; reduce over the 16 lanes of each half-warp)
    float4 a_s = *(const float4*)&a_src[col4];
    float4 a_d = *(const float4*)&a_dst[col4];
    int lane = tid & 31;
#pragma unroll
    for (int r = 0; r < 8; r++) {
        int row = r0 + rg * 8 + r;
        bool ok = row < n;
        if (ok) *(float4*)&g_h2[(size_t)row * 64 + col4] =
            make_float4(acc[r][0], acc[r][1], acc[r][2], acc[r][3]);
        float s = acc[r][0] * a_s.x + acc[r][1] * a_s.y + acc[r][2] * a_s.z + acc[r][3] * a_s.w;
        float d = acc[r][0] * a_d.x + acc[r][1] * a_d.y + acc[r][2] * a_d.z + acc[r][3] * a_d.w;
#pragma unroll
        for (int o = 1; o < 16; o <<= 1) {
            s += __shfl_xor_sync(0xffffffffu, s, o);
            d += __shfl_xor_sync(0xffffffffu, d, o);
        }
        if (ok && (lane & 15) == 0) {
            g_as2[row] = s;
            g_ad2[row] = d;
        }
    }
}

// ---------------- layer-1 aggregation (+bias, +ELU) ----------------
// WARP per node; lane owns channel pair (2*lane, 2*lane+1); head h = lane>>2.
// Softmax folded; x4 unroll with independent accumulators.
__global__ void agg1_k(const float* __restrict__ b1, int n) {
    int lane = threadIdx.x & 31;
    int node = blockIdx.x * 8 + (threadIdx.x >> 5);
    if (node >= n) return;
    int h = lane >> 2;
    int c2 = lane * 2;
    int beg = g_off[node], end = g_off[node + 1];
    float adv = g_ad1[(size_t)node * 8 + h];
    float ax0 = 0.f, ay0 = 0.f, ax1 = 0.f, ay1 = 0.f;
    float ax2 = 0.f, ay2 = 0.f, ax3 = 0.f, ay3 = 0.f;
    float den0 = 0.f, den1 = 0.f, den2 = 0.f, den3 = 0.f;
    int j = beg;
    for (; j + 3 < end; j += 4) {
        int s0 = g_csr[j];
        int s1 = g_csr[j + 1];
        int s2 = g_csr[j + 2];
        int s3 = g_csr[j + 3];
        float e0 = g_as1[(size_t)s0 * 8 + h] + adv;
        float e1 = g_as1[(size_t)s1 * 8 + h] + adv;
        float e2 = g_as1[(size_t)s2 * 8 + h] + adv;
        float e3 = g_as1[(size_t)s3 * 8 + h] + adv;
        float2 v0 = *(const float2*)&g_h1[(size_t)s0 * 64 + c2];
        float2 v1 = *(const float2*)&g_h1[(size_t)s1 * 64 + c2];
        float2 v2 = *(const float2*)&g_h1[(size_t)s2 * 64 + c2];
        float2 v3 = *(const float2*)&g_h1[(size_t)s3 * 64 + c2];
        e0 = (e0 > 0.f) ? e0 : 0.2f * e0;
        e1 = (e1 > 0.f) ? e1 : 0.2f * e1;
        e2 = (e2 > 0.f) ? e2 : 0.2f * e2;
        e3 = (e3 > 0.f) ? e3 : 0.2f * e3;
        float p0 = __expf(e0);
        float p1 = __expf(e1);
        float p2 = __expf(e2);
        float p3 = __expf(e3);
        den0 += p0; den1 += p1; den2 += p2; den3 += p3;
        ax0 += p0 * v0.x; ay0 += p0 * v0.y;
        ax1 += p1 * v1.x; ay1 += p1 * v1.y;
        ax2 += p2 * v2.x; ay2 += p2 * v2.y;
        ax3 += p3 * v3.x; ay3 += p3 * v3.y;
    }
    for (; j < end; j++) {
        int s0 = g_csr[j];
        float e0 = g_as1[(size_t)s0 * 8 + h] + adv;
        e0 = (e0 > 0.f) ? e0 : 0.2f * e0;
        float p0 = __expf(e0);
        float2 v0 = *(const float2*)&g_h1[(size_t)s0 * 64 + c2];
        den0 += p0;
        ax0 += p0 * v0.x; ay0 += p0 * v0.y;
    }
    float den = (den0 + den1) + (den2 + den3);
    float rden = __fdividef(1.f, den + 1e-16f);
    float vx = ((ax0 + ax1) + (ax2 + ax3)) * rden + b1[c2];
    float vy = ((ay0 + ay1) + (ay2 + ay3)) * rden + b1[c2 + 1];
    vx = (vx > 0.f) ? vx : expm1f(vx);   // ELU
    vy = (vy > 0.f) ? vy : expm1f(vy);
    *(float2*)&g_x2[(size_t)node * 64 + c2] = make_float2(vx, vy);
}

// ---------------- layer-2 aggregation + log_softmax (warp per node) ----------------
__global__ void agg2_k(const float* __restrict__ b2, float* __restrict__ out, int n) {
    int lane = threadIdx.x & 31;
    int node = blockIdx.x * 8 + (threadIdx.x >> 5);
    if (node >= n) return;
    int c2 = lane * 2;
    int beg = g_off[node], end = g_off[node + 1];
    float adv = g_ad2[node];
    float ax0 = 0.f, ay0 = 0.f, ax1 = 0.f, ay1 = 0.f;
    float ax2 = 0.f, ay2 = 0.f, ax3 = 0.f, ay3 = 0.f;
    float den0 = 0.f, den1 = 0.f, den2 = 0.f, den3 = 0.f;
    int j = beg;
    for (; j + 3 < end; j += 4) {
        int s0 = g_csr[j];
        int s1 = g_csr[j + 1];
        int s2 = g_csr[j + 2];
        int s3 = g_csr[j + 3];
        float e0 = g_as2[s0] + adv;
        float e1 = g_as2[s1] + adv;
        float e2 = g_as2[s2] + adv;
        float e3 = g_as2[s3] + adv;
        float2 v0 = *(const float2*)&g_h2[(size_t)s0 * 64 + c2];
        float2 v1 = *(const float2*)&g_h2[(size_t)s1 * 64 + c2];
        float2 v2 = *(const float2*)&g_h2[(size_t)s2 * 64 + c2];
        float2 v3 = *(const float2*)&g_h2[(size_t)s3 * 64 + c2];
        e0 = (e0 > 0.f) ? e0 : 0.2f * e0;
        e1 = (e1 > 0.f) ? e1 : 0.2f * e1;
        e2 = (e2 > 0.f) ? e2 : 0.2f * e2;
        e3 = (e3 > 0.f) ? e3 : 0.2f * e3;
        float p0 = __expf(e0);
        float p1 = __expf(e1);
        float p2 = __expf(e2);
        float p3 = __expf(e3);
        den0 += p0; den1 += p1; den2 += p2; den3 += p3;
        ax0 += p0 * v0.x; ay0 += p0 * v0.y;
        ax1 += p1 * v1.x; ay1 += p1 * v1.y;
        ax2 += p2 * v2.x; ay2 += p2 * v2.y;
        ax3 += p3 * v3.x; ay3 += p3 * v3.y;
    }
    for (; j < end; j++) {
        int s0 = g_csr[j];
        float e0 = g_as2[s0] + adv;
        e0 = (e0 > 0.f) ? e0 : 0.2f * e0;
        float p0 = __expf(e0);
        float2 v0 = *(const float2*)&g_h2[(size_t)s0 * 64 + c2];
        den0 += p0;
        ax0 += p0 * v0.x; ay0 += p0 * v0.y;
    }
    float den = (den0 + den1) + (den2 + den3);
    float rden = __fdividef(1.f, den + 1e-16f);
    float vx = ((ax0 + ax1) + (ax2 + ax3)) * rden + b2[c2];
    float vy = ((ay0 + ay1) + (ay2 + ay3)) * rden + b2[c2 + 1];
    // log_softmax over the 64 values held 2-per-lane in this warp
    float m = fmaxf(vx, vy);
#pragma unroll
    for (int o = 16; o; o >>= 1) m = fmaxf(m, __shfl_xor_sync(0xffffffffu, m, o));
    float p = __expf(vx - m) + __expf(vy - m);
#pragma unroll
    for (int o = 16; o; o >>= 1) p += __shfl_xor_sync(0xffffffffu, p, o);
    float lt = m + logf(p);
    *(float2*)&out[(size_t)node * 64 + c2] = make_float2(vx - lt, vy - lt);
}

// ---------------- launch ----------------
extern "C" void kernel_launch(void* const* d_in, const int* in_sizes, int n_in,
                              void* d_out, int out_size) {
    const float* x   = (const float*)d_in[0];
    const int*   ei  = (const int*)  d_in[1];
    const float* W1  = (const float*)d_in[2];
    const float* as1 = (const float*)d_in[3];
    const float* ad1 = (const float*)d_in[4];
    const float* b1  = (const float*)d_in[5];
    const float* W2  = (const float*)d_in[6];
    const float* as2 = (const float*)d_in[7];
    const float* ad2 = (const float*)d_in[8];
    const float* b2  = (const float*)d_in[9];

    int n = in_sizes[0] / 128;
    int E = in_sizes[1] / 2;
    int nb = (n + 255) / 256;

    // CSR by destination (multi-block scan)
    void* cnt_ptr = nullptr;
    cudaGetSymbolAddress(&cnt_ptr, g_cnt);
    cudaMemsetAsync(cnt_ptr, 0, (size_t)n * sizeof(int));
    count_k<<<(E + 255) / 256, 256>>>(ei, E);
    bsum_k<<<nb, 256>>>(n);
    bscan_k<<<1, 512>>>(nb);
    emit_k<<<nb, 256>>>(n, E + n);
    fill_k<<<(E + 255) / 256, 256>>>(ei, E);

    // Layer 1 (alpha1 fused into gemm1 epilogue)
    gemm1_k<<<(n + 63) / 64, 128>>>(x, W1, as1, ad1, n);
    agg1_k<<<(n + 7) / 8, 256>>>(b1, n);

    // Layer 2 (alpha2 fused into gemm2 epilogue)
    gemm2_k<<<(n + 63) / 64, 128>>>(W2, as2, ad2, n);
    agg2_k<<<(n + 7) / 8, 256>>>(b2, (float*)d_out, n);
}